// round 3
// baseline (speedup 1.0000x reference)
#include <cuda_runtime.h>

// SE block, one persistent kernel, 152 blocks (one per GB300 SM), grid barrier.
// x [32,256,56,56] f32. HW=3136 (=784 float4). B*C=8192 planes.
// Plane assignment: plane = bid + 152*k  (k = 0..53), so every block gets 53-54
// planes (<2% imbalance) and all 152 SMs stream.

#define B        32
#define C        256
#define BOT      32
#define HW       3136
#define HW4      784
#define BC       8192
#define GRID     152
#define NTHREADS 1024
#define MAXK     64          // >= max planes per block (54)

__device__ float d_s[BC];                       // pooled means
__device__ unsigned int d_arrive = 0;           // barrier arrival counter
__device__ volatile unsigned int d_gen = 0;     // barrier generation

__global__ void __launch_bounds__(NTHREADS, 1) se_fused_kernel(
    const float* __restrict__ x,
    const float* __restrict__ w1, const float* __restrict__ b1,
    const float* __restrict__ w2, const float* __restrict__ b2,
    float* __restrict__ out)
{
    const int tid  = threadIdx.x;
    const int warp = tid >> 5;
    const int lane = tid & 31;
    const int bid  = blockIdx.x;
    const int nk   = (BC - 1 - bid) / GRID + 1;   // planes this block owns (53/54)

    // ---------------- Phase 1: pooled sums, plane = bid + 152*k ---------------
    for (int k = warp; k < nk; k += 32) {
        const int plane = bid + GRID * k;
        const float4* __restrict__ xp =
            reinterpret_cast<const float4*>(x) + (size_t)plane * HW4;
        float s0 = 0.f, s1 = 0.f, s2 = 0.f, s3 = 0.f;
        // 784 = 6*128 + 16 : main loop 4 independent loads/iter, then tail
        #pragma unroll
        for (int i = lane; i < 768; i += 128) {
            float4 a = xp[i];
            float4 b = xp[i + 32];
            float4 c = xp[i + 64];
            float4 d = xp[i + 96];
            s0 += (a.x + a.y) + (a.z + a.w);
            s1 += (b.x + b.y) + (b.z + b.w);
            s2 += (c.x + c.y) + (c.z + c.w);
            s3 += (d.x + d.y) + (d.z + d.w);
        }
        if (lane < 16) {
            float4 t = xp[768 + lane];
            s0 += (t.x + t.y) + (t.z + t.w);
        }
        float sum = (s0 + s1) + (s2 + s3);
        #pragma unroll
        for (int o = 16; o > 0; o >>= 1)
            sum += __shfl_xor_sync(0xffffffffu, sum, o);
        if (lane == 0) d_s[plane] = sum * (1.0f / (float)HW);
    }

    // ---------------- Grid barrier (replay-safe generation scheme) ------------
    __threadfence();
    __syncthreads();
    if (tid == 0) {
        const unsigned int target = d_gen;
        const unsigned int old = atomicAdd(&d_arrive, 1);
        if (old == GRID - 1) {
            d_arrive = 0;
            __threadfence();
            d_gen = target + 1;              // release
        } else {
            while (d_gen == target) __nanosleep(64);
        }
        __threadfence();
    }
    __syncthreads();

    // ---------------- Phase 2: full MLP per block (redundant, ~free) ----------
    __shared__ float sh_s[B * (C + 1)];      // padded: bank-conflict-free (32.9KB)
    __shared__ float sh_h[B * BOT];          // h[b][o] at [b*32+o] (4KB)
    __shared__ float sh_g[MAXK];

    for (int t = tid; t < BC; t += NTHREADS) {
        const int b = t >> 8, c = t & 255;
        sh_s[b * (C + 1) + c] = d_s[t];
    }
    __syncthreads();

    {   // warp 'o' computes h[b][o] for b = lane (w1 row reads are warp-uniform)
        const int o = warp;
        const float* __restrict__ w1row = w1 + o * C;
        float acc = 0.0f;
        const float* __restrict__ srow = sh_s + lane * (C + 1);
        #pragma unroll 8
        for (int c = 0; c < C; c++)
            acc = fmaf(srow[c], __ldg(w1row + c), acc);
        sh_h[lane * BOT + o] = fmaxf(acc + __ldg(b1 + o), 0.0f);
    }
    __syncthreads();

    if (tid < nk) {                          // one thread per owned plane
        const int plane = bid + GRID * tid;
        const int b = plane >> 8, c = plane & 255;
        const float* __restrict__ hrow = sh_h + b * BOT;
        const float* __restrict__ wrow = w2 + c * BOT;
        float acc = __ldg(b2 + c);
        #pragma unroll
        for (int o = 0; o < BOT; o++)
            acc = fmaf(hrow[o], __ldg(wrow + o), acc);
        sh_g[tid] = 1.0f / (1.0f + __expf(-acc));
    }
    __syncthreads();

    // ---------------- Phase 3: scale (ldcs/stcs to protect L2-resident x) -----
    for (int k = warp; k < nk; k += 32) {
        const int plane = bid + GRID * k;
        const float g = sh_g[k];
        const float4* __restrict__ xp =
            reinterpret_cast<const float4*>(x) + (size_t)plane * HW4;
        float4* __restrict__ op =
            reinterpret_cast<float4*>(out) + (size_t)plane * HW4;
        #pragma unroll
        for (int i = lane; i < 768; i += 128) {
            float4 a = __ldcs(xp + i);
            float4 b = __ldcs(xp + i + 32);
            float4 c = __ldcs(xp + i + 64);
            float4 d = __ldcs(xp + i + 96);
            a.x *= g; a.y *= g; a.z *= g; a.w *= g;
            b.x *= g; b.y *= g; b.z *= g; b.w *= g;
            c.x *= g; c.y *= g; c.z *= g; c.w *= g;
            d.x *= g; d.y *= g; d.z *= g; d.w *= g;
            __stcs(op + i,      a);
            __stcs(op + i + 32, b);
            __stcs(op + i + 64, c);
            __stcs(op + i + 96, d);
        }
        if (lane < 16) {
            float4 t = __ldcs(xp + 768 + lane);
            t.x *= g; t.y *= g; t.z *= g; t.w *= g;
            __stcs(op + 768 + lane, t);
        }
    }
}

extern "C" void kernel_launch(void* const* d_in, const int* in_sizes, int n_in,
                              void* d_out, int out_size) {
    const float* x  = (const float*)d_in[0];
    const float* w1 = (const float*)d_in[1];
    const float* b1 = (const float*)d_in[2];
    const float* w2 = (const float*)d_in[3];
    const float* b2 = (const float*)d_in[4];
    float* out = (float*)d_out;

    se_fused_kernel<<<GRID, NTHREADS>>>(x, w1, b1, w2, b2, out);
}

// round 4
// speedup vs baseline: 1.1916x; 1.1916x over previous
#include <cuda_runtime.h>

// SE block, one persistent kernel, 152 blocks (one per GB300 SM), grid barrier.
// x [32,256,56,56] f32. HW=3136 (=784 float4). B*C=8192 planes.
//
// Phase 1: quarter-plane units (196 f4), 32768 units round-robined over all
//          4864 warps (96% utilization), MLP=7, partial sums -> d_partial.
// Phase 2: per block, rebuild the <=2 batch rows of pooled means it needs,
//          compute hidden + gates for its contiguous plane chunk.
// Phase 3: block-stride flat streaming over its contiguous chunk, MLP=8,
//          __ldcs reads (x is L2-resident from phase 1), __stcs writes.

#define C        256
#define BOT      32
#define HW       3136
#define HW4      784
#define QF4      196
#define BC       8192
#define NUNITS   (BC * 4)
#define GRID     152
#define NTHREADS 1024
#define NWARPS   (GRID * 32)

__device__ float d_partial[NUNITS];
__device__ unsigned int d_arrive = 0;
__device__ volatile unsigned int d_gen = 0;

__global__ void __launch_bounds__(NTHREADS, 1) se_fused_kernel(
    const float* __restrict__ x,
    const float* __restrict__ w1, const float* __restrict__ b1,
    const float* __restrict__ w2, const float* __restrict__ b2,
    float* __restrict__ out)
{
    const int tid   = threadIdx.x;
    const int warp  = tid >> 5;
    const int lane  = tid & 31;
    const int bid   = blockIdx.x;
    const int gwarp = bid * 32 + warp;

    // ---------------- Phase 1: quarter-plane partial sums ---------------------
    for (int u = gwarp; u < NUNITS; u += NWARPS) {
        const int plane = u >> 2;
        const int q     = u & 3;
        const float4* __restrict__ xp =
            reinterpret_cast<const float4*>(x) + (size_t)plane * HW4 + q * QF4;
        // 196 = 6*32 + 4 : 6 unguarded + 1 predicated load, all independent
        float4 v0 = xp[lane];
        float4 v1 = xp[lane + 32];
        float4 v2 = xp[lane + 64];
        float4 v3 = xp[lane + 96];
        float4 v4 = xp[lane + 128];
        float4 v5 = xp[lane + 160];
        float4 v6 = make_float4(0.f, 0.f, 0.f, 0.f);
        if (lane < 4) v6 = xp[lane + 192];
        float s0 = (v0.x + v0.y) + (v0.z + v0.w);
        float s1 = (v1.x + v1.y) + (v1.z + v1.w);
        float s2 = (v2.x + v2.y) + (v2.z + v2.w);
        float s3 = (v3.x + v3.y) + (v3.z + v3.w);
        s0 += (v4.x + v4.y) + (v4.z + v4.w);
        s1 += (v5.x + v5.y) + (v5.z + v5.w);
        s2 += (v6.x + v6.y) + (v6.z + v6.w);
        float sum = (s0 + s1) + (s2 + s3);
        #pragma unroll
        for (int o = 16; o > 0; o >>= 1)
            sum += __shfl_xor_sync(0xffffffffu, sum, o);
        if (lane == 0) d_partial[u] = sum;
    }

    // ---------------- Grid barrier (replay-safe generation scheme) ------------
    __threadfence();
    __syncthreads();
    if (tid == 0) {
        const unsigned int target = d_gen;
        const unsigned int old = atomicAdd(&d_arrive, 1);
        if (old == GRID - 1) {
            d_arrive = 0;
            __threadfence();
            d_gen = target + 1;              // release
        } else {
            while (d_gen == target) __nanosleep(64);
        }
        __threadfence();
    }
    __syncthreads();

    // ---------------- Phase 2: means -> hidden -> gates for our chunk ---------
    const int p0 = (int)(((long long)bid * BC) / GRID);
    const int p1 = (int)(((long long)(bid + 1) * BC) / GRID);
    const int nk = p1 - p0;                  // 53 or 54
    const int b0 = p0 >> 8;
    const int nb = ((p1 - 1) >> 8) - b0 + 1; // 1 or 2

    __shared__ float sh_s[2][C];
    __shared__ float sh_h[2][BOT];
    __shared__ float sh_g[64];

    for (int idx = tid; idx < nb * C; idx += NTHREADS) {
        const int bi = idx >> 8, c = idx & 255;
        const int plane = (b0 + bi) * C + c;
        const float* __restrict__ pp = d_partial + plane * 4;
        const float s = (pp[0] + pp[1]) + (pp[2] + pp[3]);
        sh_s[bi][c] = s * (1.0f / (float)HW);
    }
    __syncthreads();

    for (int j = warp; j < nb * BOT; j += 32) {
        const int bi = j >> 5, o = j & 31;
        const float* __restrict__ w1row = w1 + o * C;
        float acc = 0.0f;
        #pragma unroll
        for (int k = 0; k < 8; k++) {
            const int c = lane + 32 * k;
            acc = fmaf(sh_s[bi][c], __ldg(w1row + c), acc);
        }
        #pragma unroll
        for (int off = 16; off > 0; off >>= 1)
            acc += __shfl_xor_sync(0xffffffffu, acc, off);
        if (lane == 0) sh_h[bi][o] = fmaxf(acc + __ldg(b1 + o), 0.0f);
    }
    __syncthreads();

    if (tid < nk) {
        const int plane = p0 + tid;
        const int c = plane & 255;
        const int bi = (plane >> 8) - b0;
        const float* __restrict__ wrow = w2 + c * BOT;
        float acc = __ldg(b2 + c);
        #pragma unroll
        for (int o = 0; o < BOT; o++)
            acc = fmaf(sh_h[bi][o], __ldg(wrow + o), acc);
        sh_g[tid] = 1.0f / (1.0f + __expf(-acc));
    }
    __syncthreads();

    // ---------------- Phase 3: flat streaming over contiguous chunk -----------
    const size_t jbase = (size_t)p0 * HW4;
    const unsigned int total = (unsigned int)nk * HW4;   // <= 42336
    const float4* __restrict__ x4 = reinterpret_cast<const float4*>(x) + jbase;
    float4* __restrict__ o4 = reinterpret_cast<float4*>(out) + jbase;

    unsigned int i = tid;
    for (; i + 7 * NTHREADS < total; i += 8 * NTHREADS) {
        float4 v0 = __ldcs(x4 + i);
        float4 v1 = __ldcs(x4 + i + 1 * NTHREADS);
        float4 v2 = __ldcs(x4 + i + 2 * NTHREADS);
        float4 v3 = __ldcs(x4 + i + 3 * NTHREADS);
        float4 v4 = __ldcs(x4 + i + 4 * NTHREADS);
        float4 v5 = __ldcs(x4 + i + 5 * NTHREADS);
        float4 v6 = __ldcs(x4 + i + 6 * NTHREADS);
        float4 v7 = __ldcs(x4 + i + 7 * NTHREADS);
        float g0 = sh_g[(i) / HW4];
        float g1 = sh_g[(i + 1 * NTHREADS) / HW4];
        float g2 = sh_g[(i + 2 * NTHREADS) / HW4];
        float g3 = sh_g[(i + 3 * NTHREADS) / HW4];
        float g4 = sh_g[(i + 4 * NTHREADS) / HW4];
        float g5 = sh_g[(i + 5 * NTHREADS) / HW4];
        float g6 = sh_g[(i + 6 * NTHREADS) / HW4];
        float g7 = sh_g[(i + 7 * NTHREADS) / HW4];
        v0.x *= g0; v0.y *= g0; v0.z *= g0; v0.w *= g0;
        v1.x *= g1; v1.y *= g1; v1.z *= g1; v1.w *= g1;
        v2.x *= g2; v2.y *= g2; v2.z *= g2; v2.w *= g2;
        v3.x *= g3; v3.y *= g3; v3.z *= g3; v3.w *= g3;
        v4.x *= g4; v4.y *= g4; v4.z *= g4; v4.w *= g4;
        v5.x *= g5; v5.y *= g5; v5.z *= g5; v5.w *= g5;
        v6.x *= g6; v6.y *= g6; v6.z *= g6; v6.w *= g6;
        v7.x *= g7; v7.y *= g7; v7.z *= g7; v7.w *= g7;
        __stcs(o4 + i,                v0);
        __stcs(o4 + i + 1 * NTHREADS, v1);
        __stcs(o4 + i + 2 * NTHREADS, v2);
        __stcs(o4 + i + 3 * NTHREADS, v3);
        __stcs(o4 + i + 4 * NTHREADS, v4);
        __stcs(o4 + i + 5 * NTHREADS, v5);
        __stcs(o4 + i + 6 * NTHREADS, v6);
        __stcs(o4 + i + 7 * NTHREADS, v7);
    }
    for (; i < total; i += NTHREADS) {
        const float g = sh_g[i / HW4];
        float4 v = __ldcs(x4 + i);
        v.x *= g; v.y *= g; v.z *= g; v.w *= g;
        __stcs(o4 + i, v);
    }
}

extern "C" void kernel_launch(void* const* d_in, const int* in_sizes, int n_in,
                              void* d_out, int out_size) {
    const float* x  = (const float*)d_in[0];
    const float* w1 = (const float*)d_in[1];
    const float* b1 = (const float*)d_in[2];
    const float* w2 = (const float*)d_in[3];
    const float* b2 = (const float*)d_in[4];
    float* out = (float*)d_out;

    se_fused_kernel<<<GRID, NTHREADS>>>(x, w1, b1, w2, b2, out);
}

// round 5
// speedup vs baseline: 1.2510x; 1.0498x over previous
#include <cuda_runtime.h>

// SE block, one persistent kernel, 152 blocks (one per GB300 SM), grid barrier.
// x [32,256,56,56] f32. HW=3136 (=784 float4). B*C=8192 planes.
//
// Block bid owns contiguous planes [p0,p1) (53/54). Phase 1 reduces them via
// block-local quarter-plane units (partials in smem, only 54 floats to gmem).
// Phase 3 re-streams the SAME chunk in REVERSE order so the tail of the chunk
// (most recently loaded in phase 1) is harvested from L1/L2 while hot.

#define C        256
#define BOT      32
#define HW       3136
#define HW4      784
#define QF4      196
#define BC       8192
#define GRID     152
#define NTHREADS 1024

__device__ float d_s[BC];                       // pooled means
__device__ unsigned int d_arrive = 0;
__device__ volatile unsigned int d_gen = 0;

__global__ void __launch_bounds__(NTHREADS, 1) se_fused_kernel(
    const float* __restrict__ x,
    const float* __restrict__ w1, const float* __restrict__ b1,
    const float* __restrict__ w2, const float* __restrict__ b2,
    float* __restrict__ out)
{
    const int tid  = threadIdx.x;
    const int warp = tid >> 5;
    const int lane = tid & 31;
    const int bid  = blockIdx.x;

    const int p0 = (int)(((long long)bid * BC) / GRID);
    const int p1 = (int)(((long long)(bid + 1) * BC) / GRID);
    const int nk = p1 - p0;                  // 53 or 54 planes
    const int nu = nk * 4;                   // quarter-plane units (212/216)

    __shared__ float sh_part[216];
    __shared__ float sh_s[2][C];
    __shared__ float sh_h[2][BOT];
    __shared__ float sh_g[64];

    // ---------------- Phase 1: block-local quarter-plane partial sums ---------
    const float4* __restrict__ xb =
        reinterpret_cast<const float4*>(x) + (size_t)p0 * HW4;
    for (int u = warp; u < nu; u += 32) {
        const float4* __restrict__ xp = xb + (size_t)u * QF4;
        float4 v0 = xp[lane];
        float4 v1 = xp[lane + 32];
        float4 v2 = xp[lane + 64];
        float4 v3 = xp[lane + 96];
        float4 v4 = xp[lane + 128];
        float4 v5 = xp[lane + 160];
        float4 v6 = make_float4(0.f, 0.f, 0.f, 0.f);
        if (lane < 4) v6 = xp[lane + 192];
        float s0 = (v0.x + v0.y) + (v0.z + v0.w);
        float s1 = (v1.x + v1.y) + (v1.z + v1.w);
        float s2 = (v2.x + v2.y) + (v2.z + v2.w);
        float s3 = (v3.x + v3.y) + (v3.z + v3.w);
        s0 += (v4.x + v4.y) + (v4.z + v4.w);
        s1 += (v5.x + v5.y) + (v5.z + v5.w);
        s2 += (v6.x + v6.y) + (v6.z + v6.w);
        float sum = (s0 + s1) + (s2 + s3);
        #pragma unroll
        for (int o = 16; o > 0; o >>= 1)
            sum += __shfl_xor_sync(0xffffffffu, sum, o);
        if (lane == 0) sh_part[u] = sum;
    }
    __syncthreads();
    if (tid < nk) {
        const float* __restrict__ pp = sh_part + 4 * tid;
        d_s[p0 + tid] = ((pp[0] + pp[1]) + (pp[2] + pp[3])) * (1.0f / (float)HW);
    }

    // ---------------- Grid barrier (replay-safe generation scheme) ------------
    __threadfence();
    __syncthreads();
    if (tid == 0) {
        const unsigned int target = d_gen;
        const unsigned int old = atomicAdd(&d_arrive, 1);
        if (old == GRID - 1) {
            d_arrive = 0;
            __threadfence();
            d_gen = target + 1;              // release
        } else {
            while (d_gen == target) __nanosleep(64);
        }
        __threadfence();
    }
    __syncthreads();

    // ---------------- Phase 2: means -> hidden -> gates for our chunk ---------
    const int b0 = p0 >> 8;
    const int nb = ((p1 - 1) >> 8) - b0 + 1; // 1 or 2 batch rows needed

    for (int idx = tid; idx < nb * C; idx += NTHREADS)
        sh_s[idx >> 8][idx & 255] = d_s[b0 * C + idx];
    __syncthreads();

    for (int j = warp; j < nb * BOT; j += 32) {
        const int bi = j >> 5, o = j & 31;
        const float* __restrict__ w1row = w1 + o * C;
        float acc = 0.0f;
        #pragma unroll
        for (int k = 0; k < 8; k++) {
            const int c = lane + 32 * k;
            acc = fmaf(sh_s[bi][c], __ldg(w1row + c), acc);
        }
        #pragma unroll
        for (int off = 16; off > 0; off >>= 1)
            acc += __shfl_xor_sync(0xffffffffu, acc, off);
        if (lane == 0) sh_h[bi][o] = fmaxf(acc + __ldg(b1 + o), 0.0f);
    }
    __syncthreads();

    if (tid < nk) {
        const int plane = p0 + tid;
        const int c = plane & 255;
        const int bi = (plane >> 8) - b0;
        const float* __restrict__ wrow = w2 + c * BOT;
        float acc = __ldg(b2 + c);
        #pragma unroll
        for (int o = 0; o < BOT; o++)
            acc = fmaf(sh_h[bi][o], __ldg(wrow + o), acc);
        sh_g[tid] = 1.0f / (1.0f + __expf(-acc));
    }
    __syncthreads();

    // ---------------- Phase 3: REVERSE flat streaming over the same chunk -----
    const unsigned int total = (unsigned int)nk * HW4;       // <= 42336
    const int nfull = (int)(total / (8u * NTHREADS));        // full 8-wide iters
    const float4* __restrict__ x4 = xb;
    float4* __restrict__ o4 = reinterpret_cast<float4*>(out) + (size_t)p0 * HW4;

    // tail first (highest addresses = hottest in L1/L2)
    for (unsigned int i = (unsigned int)nfull * 8u * NTHREADS + tid; i < total;
         i += NTHREADS) {
        const float g = sh_g[i / HW4];
        float4 v = __ldcs(x4 + i);
        v.x *= g; v.y *= g; v.z *= g; v.w *= g;
        __stcs(o4 + i, v);
    }
    for (int it = nfull - 1; it >= 0; --it) {
        const unsigned int i = (unsigned int)it * 8u * NTHREADS + tid;
        float4 v0 = __ldcs(x4 + i);
        float4 v1 = __ldcs(x4 + i + 1 * NTHREADS);
        float4 v2 = __ldcs(x4 + i + 2 * NTHREADS);
        float4 v3 = __ldcs(x4 + i + 3 * NTHREADS);
        float4 v4 = __ldcs(x4 + i + 4 * NTHREADS);
        float4 v5 = __ldcs(x4 + i + 5 * NTHREADS);
        float4 v6 = __ldcs(x4 + i + 6 * NTHREADS);
        float4 v7 = __ldcs(x4 + i + 7 * NTHREADS);
        const float g0 = sh_g[(i) / HW4];
        const float g1 = sh_g[(i + 1 * NTHREADS) / HW4];
        const float g2 = sh_g[(i + 2 * NTHREADS) / HW4];
        const float g3 = sh_g[(i + 3 * NTHREADS) / HW4];
        const float g4 = sh_g[(i + 4 * NTHREADS) / HW4];
        const float g5 = sh_g[(i + 5 * NTHREADS) / HW4];
        const float g6 = sh_g[(i + 6 * NTHREADS) / HW4];
        const float g7 = sh_g[(i + 7 * NTHREADS) / HW4];
        v0.x *= g0; v0.y *= g0; v0.z *= g0; v0.w *= g0;
        v1.x *= g1; v1.y *= g1; v1.z *= g1; v1.w *= g1;
        v2.x *= g2; v2.y *= g2; v2.z *= g2; v2.w *= g2;
        v3.x *= g3; v3.y *= g3; v3.z *= g3; v3.w *= g3;
        v4.x *= g4; v4.y *= g4; v4.z *= g4; v4.w *= g4;
        v5.x *= g5; v5.y *= g5; v5.z *= g5; v5.w *= g5;
        v6.x *= g6; v6.y *= g6; v6.z *= g6; v6.w *= g6;
        v7.x *= g7; v7.y *= g7; v7.z *= g7; v7.w *= g7;
        __stcs(o4 + i,                v0);
        __stcs(o4 + i + 1 * NTHREADS, v1);
        __stcs(o4 + i + 2 * NTHREADS, v2);
        __stcs(o4 + i + 3 * NTHREADS, v3);
        __stcs(o4 + i + 4 * NTHREADS, v4);
        __stcs(o4 + i + 5 * NTHREADS, v5);
        __stcs(o4 + i + 6 * NTHREADS, v6);
        __stcs(o4 + i + 7 * NTHREADS, v7);
    }
}

extern "C" void kernel_launch(void* const* d_in, const int* in_sizes, int n_in,
                              void* d_out, int out_size) {
    const float* x  = (const float*)d_in[0];
    const float* w1 = (const float*)d_in[1];
    const float* b1 = (const float*)d_in[2];
    const float* w2 = (const float*)d_in[3];
    const float* b2 = (const float*)d_in[4];
    float* out = (float*)d_out;

    se_fused_kernel<<<GRID, NTHREADS>>>(x, w1, b1, w2, b2, out);
}